// round 1
// baseline (speedup 1.0000x reference)
#include <cuda_runtime.h>
#include <cuda_bf16.h>
#include <math.h>

// Problem constants (fixed by setup_inputs): B=32, N=M=1024, F=4
#define BB   32
#define NN   1024
#define MMM  1024
#define LL   (NN + MMM - 1)   // 2047

// Move matrix, diagonal-major: moves[b][k][i], stride 2048*1024 per batch (=2^21)
__device__ unsigned char g_moves[(size_t)BB * 2048 * 1024];
// Per-batch losses (deterministic final sum)
__device__ float g_loss[BB];

// ---------------------------------------------------------------------------
// Forward DP: one CTA per batch, one thread per row i.
// Registers d1 = D[i, j-1], d2 = D[i, j-2]; neighbor row values via shfl_up.
// Warp-boundary values cross warps through double-buffered smem (1 bar/diag).
// ---------------------------------------------------------------------------
__global__ __launch_bounds__(1024, 1)
void dtw_forward(const float* __restrict__ preds, const float* __restrict__ targs)
{
    const int b    = blockIdx.x;
    const int i    = threadIdx.x;
    const int lane = i & 31;
    const int warp = i >> 5;

    __shared__ float tx[MMM], ty[MMM];
    __shared__ float sb1[2][32];   // lane-31 d1 per warp, double buffered
    __shared__ float sb2[2][32];   // lane-31 d2 per warp, double buffered

    const float* pb = preds + (size_t)b * NN  * 4;
    const float* tb = targs + (size_t)b * MMM * 4;

    // Basis coords (features 0,1)
    float2 tv = *(const float2*)(tb + (size_t)i * 4);
    tx[i] = tv.x; ty[i] = tv.y;
    float2 pv = *(const float2*)(pb + (size_t)i * 4);
    const float px = pv.x, py = pv.y;
    __syncthreads();

    const float INF = __int_as_float(0x7f800000);
    float d1 = INF;   // D[i, (k-1)-i]
    float d2 = INF;   // D[i, (k-2)-i]

    unsigned char* mbase = g_moves + ((size_t)b << 21) + i;

    for (int k = 0; k < LL; ++k) {
        float up = __shfl_up_sync(0xffffffffu, d1, 1);  // D[i-1, j]
        float dg = __shfl_up_sync(0xffffffffu, d2, 1);  // D[i-1, j-1]
        if (lane == 0) {
            if (warp == 0) { up = INF; dg = INF; }
            else {
                up = sb1[(k + 1) & 1][warp - 1];
                dg = sb2[(k + 1) & 1][warp - 1];
            }
        }
        const float lf = d1;                             // D[i, j-1]

        const int j = k - i;
        float cur = INF;
        if ((unsigned)j < (unsigned)MMM) {
            float best = fminf(fminf(up, dg), lf);       // same order as reference
            if (isinf(best)) best = 0.0f;                // fires only at (0,0)
            const float dx = px - tx[j];
            const float dy = py - ty[j];
            const float c  = sqrtf(dx * dx + dy * dy);
            cur = c + best;

            // argmin over [dg, up, lf], first-minimum tie-break (matches jnp.argmin)
            int   m  = 0;
            float bm = dg;
            if (up < bm) { bm = up; m = 1; }
            if (lf < bm) { m = 2; }
            mbase[(size_t)k << 10] = (unsigned char)m;   // coalesced over i
        }

        if (lane == 31) { sb1[k & 1][warp] = cur; sb2[k & 1][warp] = d1; }
        d2 = d1;
        d1 = cur;
        __syncthreads();
    }
}

// ---------------------------------------------------------------------------
// Backtrack (thread 0 walks move matrix) + block-parallel path loss.
// ---------------------------------------------------------------------------
__global__ __launch_bounds__(256, 1)
void dtw_backtrack(const float* __restrict__ preds, const float* __restrict__ targs,
                   const float* __restrict__ subcoef)
{
    const int b = blockIdx.x;
    __shared__ unsigned int path[LL];    // packed (i<<16 | j)
    __shared__ int pathLen;
    __shared__ float warp_sums[8];

    if (threadIdx.x == 0) {
        const unsigned char* mv = g_moves + ((size_t)b << 21);
        int i = NN - 1, j = MMM - 1;
        int cnt = 0;
        while (true) {
            path[cnt++] = ((unsigned)i << 16) | (unsigned)j;
            if ((i | j) == 0) break;
            const unsigned m = mv[((size_t)(i + j) << 10) + (size_t)i];
            // m==0: diag, m==1: up, m==2: left
            if (m != 2) --i;
            if (m != 1) --j;
        }
        pathLen = cnt;
    }
    __syncthreads();

    const float s0 = subcoef[0];
    const float s1 = subcoef[1];
    const int   len = pathLen;

    float acc = 0.0f;
    const float* pbase = preds + (size_t)b * NN  * 4;
    const float* tbase = targs + (size_t)b * MMM * 4;
    for (int t = threadIdx.x; t < len; t += blockDim.x) {
        const unsigned pk = path[t];
        const int a  = (int)(pk >> 16);
        const int bb = (int)(pk & 0xffffu);
        const float2 pp = *(const float2*)(pbase + (size_t)a  * 4);
        const float2 tt = *(const float2*)(tbase + (size_t)bb * 4);
        acc += fabsf(pp.x - tt.x) * s0 + fabsf(pp.y - tt.y) * s1;
    }

    // block reduce (8 warps)
    #pragma unroll
    for (int off = 16; off > 0; off >>= 1)
        acc += __shfl_down_sync(0xffffffffu, acc, off);
    if ((threadIdx.x & 31) == 0) warp_sums[threadIdx.x >> 5] = acc;
    __syncthreads();
    if (threadIdx.x == 0) {
        float tot = 0.0f;
        #pragma unroll
        for (int w = 0; w < 8; ++w) tot += warp_sums[w];
        g_loss[b] = tot;
    }
}

// Deterministic fixed-order final sum
__global__ void dtw_finalize(float* __restrict__ out)
{
    float tot = 0.0f;
    #pragma unroll
    for (int b = 0; b < BB; ++b) tot += g_loss[b];
    out[0] = tot;
}

extern "C" void kernel_launch(void* const* d_in, const int* in_sizes, int n_in,
                              void* d_out, int out_size)
{
    const float* preds   = (const float*)d_in[0];
    const float* targs   = (const float*)d_in[1];
    const float* subcoef = (const float*)d_in[2];
    float* out = (float*)d_out;

    dtw_forward  <<<BB, 1024>>>(preds, targs);
    dtw_backtrack<<<BB, 256 >>>(preds, targs, subcoef);
    dtw_finalize <<<1, 1>>>(out);
}

// round 2
// speedup vs baseline: 1.6293x; 1.6293x over previous
#include <cuda_runtime.h>
#include <cuda_bf16.h>
#include <math.h>

// Problem constants (fixed by setup_inputs): B=32, N=M=1024, F=4
#define BB   32
#define NN   1024
#define MMM  1024
#define LL   (NN + MMM - 1)   // 2047
#define TT   256              // forward threads
#define RR   4                // rows per thread
#define STEPS (MMM + TT - 1)  // 1279
#define NWARP (TT / 32)

// Move matrix, column-major per batch: moves[b][j][i]  (j = targ col, i = pred row)
// +64 pad: backtrack windows may over-read up to 15B past the last cell.
__device__ unsigned char g_moves[(size_t)BB * NN * MMM + 64];
__device__ float g_loss[BB];

// ---------------------------------------------------------------------------
// Forward DP, row-banded: one CTA per batch, thread t owns rows 4t..4t+3.
// At step s, thread t computes column c = s - t for its 4 rows.
// left/diag come from its own registers; band-boundary (up/diag for row 4t)
// comes from thread t-1's bottom-row values at steps s-1 / s-2 via shfl,
// with warp boundaries through double-buffered smem (1 barrier per step).
// ---------------------------------------------------------------------------
__global__ __launch_bounds__(TT, 1)
void dtw_forward(const float* __restrict__ preds, const float* __restrict__ targs)
{
    const int b    = blockIdx.x;
    const int t    = threadIdx.x;
    const int lane = t & 31;
    const int warp = t >> 5;

    __shared__ float tx[MMM], ty[MMM];
    __shared__ float sb1[2][NWARP], sb2[2][NWARP];

    const float* pb = preds + (size_t)b * NN  * 4;
    const float* tb = targs + (size_t)b * MMM * 4;

    const float INF = __int_as_float(0x7f800000);

    float px[RR], py[RR];
    #pragma unroll
    for (int q = 0; q < RR; ++q) {
        const int idx = t * RR + q;
        const float2 tv = *(const float2*)(tb + (size_t)idx * 4);
        tx[idx] = tv.x; ty[idx] = tv.y;
        const float2 pv = *(const float2*)(pb + (size_t)idx * 4);
        px[q] = pv.x; py[q] = pv.y;
    }
    if (t < 2 * NWARP) { ((float*)sb1)[t] = INF; ((float*)sb2)[t] = INF; }
    __syncthreads();

    float left[RR];
    #pragma unroll
    for (int q = 0; q < RR; ++q) left[q] = INF;
    float last1 = INF;   // D[4t+3][c-1] after each step
    float last2 = INF;   // D[4t+3][c-2]

    unsigned char* mb = g_moves + ((size_t)b << 20) + t * RR;

    for (int s = 0; s < STEPS; ++s) {
        // Neighbor band's bottom-row values: up0 = D[4t-1][c], dg0 = D[4t-1][c-1]
        float up0 = __shfl_up_sync(0xffffffffu, last1, 1);
        float dg0 = __shfl_up_sync(0xffffffffu, last2, 1);
        if (lane == 0) {
            if (warp == 0) { up0 = INF; dg0 = INF; }
            else {
                up0 = sb1[(s + 1) & 1][warp - 1];
                dg0 = sb2[(s + 1) & 1][warp - 1];
            }
        }

        const int c = s - t;
        if ((unsigned)c < (unsigned)MMM) {
            const float txc = tx[c], tyc = ty[c];
            float up = up0, dg = dg0;
            unsigned char mq[RR];
            #pragma unroll
            for (int q = 0; q < RR; ++q) {
                const float lf = left[q];
                float best = fminf(fminf(up, dg), lf);
                // argmin over [dg, up, lf], first-minimum tie-break (jnp.argmin)
                int m = 0; float bm = dg;
                if (up < bm) { bm = up; m = 1; }
                if (lf < bm) { m = 2; }
                if (isinf(best)) best = 0.0f;            // only fires at (0,0)
                const float dx = px[q] - txc;
                const float dy = py[q] - tyc;
                const float cur = sqrtf(fmaf(dx, dx, dy * dy)) + best;
                dg = lf;          // diag for next row = old left of this row
                left[q] = cur;
                up = cur;         // up for next row = this row, same column
                mq[q] = (unsigned char)m;
            }
            uchar4 mv; mv.x = mq[0]; mv.y = mq[1]; mv.z = mq[2]; mv.w = mq[3];
            *(uchar4*)(mb + ((size_t)c << 10)) = mv;
            last2 = last1;
            last1 = left[RR - 1];
        }
        // (values freeze once c >= M, which is exactly what downstream threads need)
        if (lane == 31) { sb1[s & 1][warp] = last1; sb2[s & 1][warp] = last2; }
        __syncthreads();
    }
}

// ---------------------------------------------------------------------------
// Backtrack with windowing: each step moves i and/or j down by <=1, so from
// (i,j) the next >=31 steps stay in a 48-row x 32-col window. Warp 0 bulk
// loads the window into smem (parallel LDGs, one L2 round trip), thread 0
// walks it via cheap LDS chain. Then 256 threads compute the path loss.
// ---------------------------------------------------------------------------
__global__ __launch_bounds__(256, 1)
void dtw_backtrack(const float* __restrict__ preds, const float* __restrict__ targs,
                   const float* __restrict__ subcoef)
{
    const int b = blockIdx.x;
    __shared__ __align__(16) unsigned char win[32][48];  // [colOff][rowOff]
    __shared__ unsigned int path[LL];    // packed (i<<16 | j)
    __shared__ int s_i, s_j, s_cnt;
    __shared__ float warp_sums[8];

    if (threadIdx.x < 32) {
        const unsigned char* mvb = g_moves + ((size_t)b << 20);
        int i = NN - 1, j = MMM - 1, cnt = 1;
        if (threadIdx.x == 0) path[0] = ((unsigned)i << 16) | (unsigned)j;

        while (i | j) {
            const int ilo = max(i - 31, 0) & ~15;   // 16B-aligned row base; i-ilo in [0,46]
            const int jlo = max(j - 31, 0);

            // Load 48 rows x 32 cols: lane l takes column jlo+l
            {
                const int l = threadIdx.x;
                const unsigned char* src = mvb + (((size_t)(jlo + l)) << 10) + ilo;
                const uint4 v0 = *(const uint4*)(src);
                const uint4 v1 = *(const uint4*)(src + 16);
                const uint4 v2 = *(const uint4*)(src + 32);
                *(uint4*)&win[l][0]  = v0;
                *(uint4*)&win[l][16] = v1;
                *(uint4*)&win[l][32] = v2;
            }
            __syncwarp();

            if (threadIdx.x == 0) {
                while ((i >= ilo) && (j >= jlo) && (i | j)) {
                    const unsigned m = win[j - jlo][i - ilo];
                    // m==0: diag, m==1: up, m==2: left
                    i -= (m != 2);
                    j -= (m != 1);
                    path[cnt++] = ((unsigned)i << 16) | (unsigned)j;
                }
                s_i = i; s_j = j; s_cnt = cnt;
            }
            __syncwarp();
            i = s_i; j = s_j; cnt = s_cnt;
        }
        if (threadIdx.x == 0) s_cnt = cnt;
    }
    __syncthreads();

    const float s0 = subcoef[0];
    const float s1 = subcoef[1];
    const int   len = s_cnt;

    float acc = 0.0f;
    const float* pbase = preds + (size_t)b * NN  * 4;
    const float* tbase = targs + (size_t)b * MMM * 4;
    for (int tt = threadIdx.x; tt < len; tt += blockDim.x) {
        const unsigned pk = path[tt];
        const int a  = (int)(pk >> 16);
        const int bb = (int)(pk & 0xffffu);
        const float2 pp = *(const float2*)(pbase + (size_t)a  * 4);
        const float2 tv = *(const float2*)(tbase + (size_t)bb * 4);
        acc += fabsf(pp.x - tv.x) * s0 + fabsf(pp.y - tv.y) * s1;
    }

    #pragma unroll
    for (int off = 16; off > 0; off >>= 1)
        acc += __shfl_down_sync(0xffffffffu, acc, off);
    if ((threadIdx.x & 31) == 0) warp_sums[threadIdx.x >> 5] = acc;
    __syncthreads();
    if (threadIdx.x == 0) {
        float tot = 0.0f;
        #pragma unroll
        for (int w = 0; w < 8; ++w) tot += warp_sums[w];
        g_loss[b] = tot;
    }
}

// Deterministic fixed-order final sum
__global__ void dtw_finalize(float* __restrict__ out)
{
    float tot = 0.0f;
    #pragma unroll
    for (int b = 0; b < BB; ++b) tot += g_loss[b];
    out[0] = tot;
}

extern "C" void kernel_launch(void* const* d_in, const int* in_sizes, int n_in,
                              void* d_out, int out_size)
{
    const float* preds   = (const float*)d_in[0];
    const float* targs   = (const float*)d_in[1];
    const float* subcoef = (const float*)d_in[2];
    float* out = (float*)d_out;

    dtw_forward  <<<BB, TT >>>(preds, targs);
    dtw_backtrack<<<BB, 256>>>(preds, targs, subcoef);
    dtw_finalize <<<1, 1>>>(out);
}